// round 15
// baseline (speedup 1.0000x reference)
#include <cuda_runtime.h>
#include <cuda_bf16.h>
#include <mma.h>
#include <cstdint>

using namespace nvcuda;

// Problem dims (fixed)
#define BB   64
#define TT   512
#define IDIM 256
#define HH   512
#define BTH  (BB*TT*HH)

// Recurrence decomposition: 16 clusters (batch groups) x 8 CTAs (column groups)
#define GB   16
#define GC   8
#define BPG  4
#define CPG  64
#define NCTA (GB*GC)
#define THR  256

// ------------------------------ scratch ------------------------------------
__device__ float g_xb[TT*BB*HH];              // input projection [t][b][h]
__device__ __nv_bfloat16 g_ahi[BTH];          // layer-0 output, split hi
__device__ __nv_bfloat16 g_alo[BTH];          // layer-0 output, split lo
__device__ __nv_bfloat16 g_whi0[HH*IDIM];
__device__ __nv_bfloat16 g_wlo0[HH*IDIM];
__device__ __nv_bfloat16 g_whi1[HH*HH];
__device__ __nv_bfloat16 g_wlo1[HH*HH];

// ------------------------------ merged weight split --------------------------
__global__ void conv_split2(const float* __restrict__ s0, int n0, int nb0,
                            const float* __restrict__ s1, int n1)
{
    const int b = blockIdx.x;
    if (b < nb0) {
        int i = b * 256 + threadIdx.x;
        if (i < n0) {
            float x = s0[i];
            __nv_bfloat16 h = __float2bfloat16_rn(x);
            g_whi0[i] = h;
            g_wlo0[i] = __float2bfloat16_rn(x - __bfloat162float(h));
        }
    } else {
        int i = (b - nb0) * 256 + threadIdx.x;
        if (i < n1) {
            float x = s1[i];
            __nv_bfloat16 h = __float2bfloat16_rn(x);
            g_whi1[i] = h;
            g_wlo1[i] = __float2bfloat16_rn(x - __bfloat162float(h));
        }
    }
}

// ------------------------------ wmma GEMM (bf16 x3 split, 128x64 CTA tile) ---
// Y[t][b][n] = sum_k A[m][k]*W[n][k] + b1[n] + b2[n],  m = b*TT + t
// CTA tile 128(m) x 64(n); 8 warps as 4(m) x 2(n); warp tile 32x32 with
// 2x2 accumulator fragments (0.67 fragment-loads per mma vs 1.0 before).
// amode 0: A fp32, hi/lo split during staging. amode 1: pre-split bf16 A.
#define KC   64
#define LDS2 72
#define MT   128

__device__ __forceinline__ void split16_store(
    const float* __restrict__ srcf, __nv_bfloat16* dH16, __nv_bfloat16* dL16)
{
    const float4* src = reinterpret_cast<const float4*>(srcf);
    float v[16];
#pragma unroll
    for (int j = 0; j < 4; ++j) {
        float4 f = src[j];
        v[j*4+0] = f.x; v[j*4+1] = f.y; v[j*4+2] = f.z; v[j*4+3] = f.w;
    }
    uint32_t ph[8], pl[8];
#pragma unroll
    for (int i = 0; i < 8; ++i) {
        __nv_bfloat16 h0b = __float2bfloat16_rn(v[2*i]);
        __nv_bfloat16 h1b = __float2bfloat16_rn(v[2*i+1]);
        __nv_bfloat16 l0b = __float2bfloat16_rn(v[2*i]   - __bfloat162float(h0b));
        __nv_bfloat16 l1b = __float2bfloat16_rn(v[2*i+1] - __bfloat162float(h1b));
        ph[i] = (uint32_t)__bfloat16_as_ushort(h0b) |
                ((uint32_t)__bfloat16_as_ushort(h1b) << 16);
        pl[i] = (uint32_t)__bfloat16_as_ushort(l0b) |
                ((uint32_t)__bfloat16_as_ushort(l1b) << 16);
    }
    uint4* dH = reinterpret_cast<uint4*>(dH16);
    uint4* dL = reinterpret_cast<uint4*>(dL16);
    dH[0] = make_uint4(ph[0],ph[1],ph[2],ph[3]);
    dH[1] = make_uint4(ph[4],ph[5],ph[6],ph[7]);
    dL[0] = make_uint4(pl[0],pl[1],pl[2],pl[3]);
    dL[1] = make_uint4(pl[4],pl[5],pl[6],pl[7]);
}

// smem: sAh[128*LDS2] sAl[128*LDS2] sBh[64*LDS2] sBl[64*LDS2] bf16 = 55296 B
#define GSM_BYTES ((MT + MT + 64 + 64) * LDS2 * 2)

__global__ void __launch_bounds__(256) gemm_wmma(
    const float* __restrict__ Afp,
    const __nv_bfloat16* __restrict__ Ah, const __nv_bfloat16* __restrict__ Al,
    const __nv_bfloat16* __restrict__ Bh, const __nv_bfloat16* __restrict__ Bl,
    const float* __restrict__ b1, const float* __restrict__ b2,
    int K, int amode)
{
    __shared__ char raw[GSM_BYTES];
    __nv_bfloat16* sAh = reinterpret_cast<__nv_bfloat16*>(raw);
    __nv_bfloat16* sAl = sAh + MT * LDS2;
    __nv_bfloat16* sBh = sAl + MT * LDS2;
    __nv_bfloat16* sBl = sBh + 64 * LDS2;

    const int tid = threadIdx.x;
    const int nb  = blockIdx.x;
    const int mb  = blockIdx.y;
    const int wid = tid >> 5;
    const int wr  = wid & 3;        // m-sub 0..3 (32 rows each)
    const int wc  = wid >> 2;       // n-half 0..1 (32 cols each)

    wmma::fragment<wmma::accumulator, 16, 16, 16, float> acc[2][2];
#pragma unroll
    for (int ms = 0; ms < 2; ++ms)
#pragma unroll
        for (int ns = 0; ns < 2; ++ns) wmma::fill_fragment(acc[ms][ns], 0.0f);

    const int row = tid >> 2;            // 0..63
    const int seg = (tid & 3) * 16;

    for (int k0 = 0; k0 < K; k0 += KC) {
        __syncthreads();
        // ---- stage A (128 rows: row and row+64) ----
        if (amode == 0) {
            split16_store(Afp + (size_t)(mb*MT + row)*K + k0 + seg,
                          sAh + row*LDS2 + seg, sAl + row*LDS2 + seg);
            split16_store(Afp + (size_t)(mb*MT + 64 + row)*K + k0 + seg,
                          sAh + (64+row)*LDS2 + seg, sAl + (64+row)*LDS2 + seg);
        } else {
            const uint4* a_h = reinterpret_cast<const uint4*>(Ah + (size_t)(mb*MT + row)*K + k0 + seg);
            const uint4* a_l = reinterpret_cast<const uint4*>(Al + (size_t)(mb*MT + row)*K + k0 + seg);
            uint4* dH = reinterpret_cast<uint4*>(sAh + row*LDS2 + seg);
            uint4* dL = reinterpret_cast<uint4*>(sAl + row*LDS2 + seg);
            dH[0] = a_h[0]; dH[1] = a_h[1];
            dL[0] = a_l[0]; dL[1] = a_l[1];
            const uint4* a_h2 = reinterpret_cast<const uint4*>(Ah + (size_t)(mb*MT + 64 + row)*K + k0 + seg);
            const uint4* a_l2 = reinterpret_cast<const uint4*>(Al + (size_t)(mb*MT + 64 + row)*K + k0 + seg);
            uint4* dH2 = reinterpret_cast<uint4*>(sAh + (64+row)*LDS2 + seg);
            uint4* dL2 = reinterpret_cast<uint4*>(sAl + (64+row)*LDS2 + seg);
            dH2[0] = a_h2[0]; dH2[1] = a_h2[1];
            dL2[0] = a_l2[0]; dL2[1] = a_l2[1];
        }
        // ---- stage B (64 rows, pre-split weights) ----
        {
            const uint4* b_h = reinterpret_cast<const uint4*>(Bh + (size_t)(nb*64 + row)*K + k0 + seg);
            const uint4* b_l = reinterpret_cast<const uint4*>(Bl + (size_t)(nb*64 + row)*K + k0 + seg);
            uint4* dH = reinterpret_cast<uint4*>(sBh + row*LDS2 + seg);
            uint4* dL = reinterpret_cast<uint4*>(sBl + row*LDS2 + seg);
            dH[0] = b_h[0]; dH[1] = b_h[1];
            dL[0] = b_l[0]; dL[1] = b_l[1];
        }
        __syncthreads();

#pragma unroll
        for (int kk = 0; kk < KC / 16; ++kk) {
            wmma::fragment<wmma::matrix_a, 16, 16, 16, __nv_bfloat16, wmma::row_major> fa_h[2], fa_l[2];
#pragma unroll
            for (int ms = 0; ms < 2; ++ms) {
                wmma::load_matrix_sync(fa_h[ms], sAh + (wr*32 + ms*16)*LDS2 + kk*16, LDS2);
                wmma::load_matrix_sync(fa_l[ms], sAl + (wr*32 + ms*16)*LDS2 + kk*16, LDS2);
            }
#pragma unroll
            for (int ns = 0; ns < 2; ++ns) {
                wmma::fragment<wmma::matrix_b, 16, 16, 16, __nv_bfloat16, wmma::col_major> fb_h, fb_l;
                wmma::load_matrix_sync(fb_h, sBh + (wc*32 + ns*16)*LDS2 + kk*16, LDS2);
                wmma::load_matrix_sync(fb_l, sBl + (wc*32 + ns*16)*LDS2 + kk*16, LDS2);
#pragma unroll
                for (int ms = 0; ms < 2; ++ms) {
                    wmma::mma_sync(acc[ms][ns], fa_h[ms], fb_h, acc[ms][ns]);
                    wmma::mma_sync(acc[ms][ns], fa_h[ms], fb_l, acc[ms][ns]);
                    wmma::mma_sync(acc[ms][ns], fa_l[ms], fb_h, acc[ms][ns]);
                }
            }
        }
    }

    // Epilogue: accum -> smem (128 x LDS2 fp32 = 36.9KB, fits in raw) -> scatter.
    __syncthreads();
    float* Cs = reinterpret_cast<float*>(raw);
#pragma unroll
    for (int ms = 0; ms < 2; ++ms)
#pragma unroll
        for (int ns = 0; ns < 2; ++ns)
            wmma::store_matrix_sync(Cs + (wr*32 + ms*16)*LDS2 + wc*32 + ns*16,
                                    acc[ms][ns], LDS2, wmma::mem_row_major);
    __syncthreads();

    const int col4 = (tid & 15) * 4;
    const int n0   = nb * 64 + col4;
    float4 bias;
    bias.x = b1[n0 + 0] + b2[n0 + 0];
    bias.y = b1[n0 + 1] + b2[n0 + 1];
    bias.z = b1[n0 + 2] + b2[n0 + 2];
    bias.w = b1[n0 + 3] + b2[n0 + 3];

#pragma unroll
    for (int rr = 0; rr < 8; ++rr) {
        int r  = rr * 16 + (tid >> 4);
        int m  = mb * MT + r;
        int b_ = m >> 9;
        int t_ = m & (TT - 1);
        float4 o;
        o.x = Cs[r * LDS2 + col4 + 0] + bias.x;
        o.y = Cs[r * LDS2 + col4 + 1] + bias.y;
        o.z = Cs[r * LDS2 + col4 + 2] + bias.z;
        o.w = Cs[r * LDS2 + col4 + 3] + bias.w;
        *reinterpret_cast<float4*>(&g_xb[((size_t)t_ * BB + b_) * HH + n0]) = o;
    }
}

// ------------------------------ helpers -------------------------------------
__device__ __forceinline__ uint32_t smem_u32(const void* p) {
    uint32_t a;
    asm("{ .reg .u64 t; cvta.to.shared.u64 t, %1; cvt.u32.u64 %0, t; }"
        : "=r"(a) : "l"(p));
    return a;
}

__device__ __forceinline__ void mbar_wait(uint32_t mbar, uint32_t parity) {
    asm volatile(
        "{\n\t"
        ".reg .pred P;\n\t"
        "WL%=:\n\t"
        "mbarrier.try_wait.parity.acquire.cluster.shared::cta.b64 P, [%0], %1;\n\t"
        "@!P bra WL%=;\n\t"
        "}"
        :: "r"(mbar), "r"(parity) : "memory");
}

// ------------------------------ recurrence (proven 1396us core) -------------
#define SM_W    (HH*CPG)
#define SM_HB   (SM_W)
#define SM_RED  (SM_W + 2*BPG*HH)
#define SM_MBAR (SM_RED + 16*256)
#define REC_SMEM_BYTES ((SM_MBAR + 8) * 4)

#define STEP_TX (GC * 256 * 4)

__global__ void __launch_bounds__(THR, 1) __cluster_dims__(GC, 1, 1)
rnn_rec(const float* __restrict__ Whh,
        const float* __restrict__ h0,
        float* __restrict__ out_param,
        float* __restrict__ hn,
        int use_g0out)
{
    extern __shared__ float sm[];
    float* Wt  = sm;
    float* hb0 = sm + SM_HB;
    float* hb1 = hb0 + BPG * HH;
    float* red = sm + SM_RED;
    uint64_t* mbar = reinterpret_cast<uint64_t*>(sm + SM_MBAR);

    const int tid = threadIdx.x;
    uint32_t cg;
    asm("mov.u32 %0, %%cluster_ctarank;" : "=r"(cg));
    const int bg  = blockIdx.x >> 3;
    const int c0  = (int)cg * CPG;
    const int b0  = bg * BPG;
    const int ks  = tid >> 4;
    const int cq  = tid & 15;
    const int ob  = tid >> 6;
    const int oc  = tid & 63;

    const uint32_t mbar_u0 = smem_u32(&mbar[0]);
    const uint32_t mbar_u1 = smem_u32(&mbar[1]);
    const uint32_t hb_u0   = smem_u32(hb0);
    const uint32_t hb_u1   = smem_u32(hb1);

    for (int idx = tid; idx < CPG * (HH / 4); idx += 256) {
        int c  = idx & (CPG - 1);
        int k4 = idx >> 6;
        float4 w = *reinterpret_cast<const float4*>(Whh + (size_t)(c0 + c) * HH + k4 * 4);
        Wt[(k4 * 4 + 0) * CPG + c] = w.x;
        Wt[(k4 * 4 + 1) * CPG + c] = w.y;
        Wt[(k4 * 4 + 2) * CPG + c] = w.z;
        Wt[(k4 * 4 + 3) * CPG + c] = w.w;
    }
    {
        float4* d = reinterpret_cast<float4*>(hb0);
        const float4* s = reinterpret_cast<const float4*>(h0 + (size_t)b0 * HH);
        d[tid]       = s[tid];
        d[tid + 256] = s[tid + 256];
    }
    if (tid == 0) {
        asm volatile("mbarrier.init.shared.b64 [%0], %1;" :: "r"(mbar_u0), "r"(1u) : "memory");
        asm volatile("mbarrier.init.shared.b64 [%0], %1;" :: "r"(mbar_u1), "r"(1u) : "memory");
        asm volatile("mbarrier.arrive.expect_tx.shared.b64 _, [%0], %1;"
                     :: "r"(mbar_u0), "r"((unsigned)STEP_TX) : "memory");
        asm volatile("mbarrier.arrive.expect_tx.shared.b64 _, [%0], %1;"
                     :: "r"(mbar_u1), "r"((unsigned)STEP_TX) : "memory");
    }
    __syncthreads();
    asm volatile("barrier.cluster.arrive.aligned;" ::: "memory");
    asm volatile("barrier.cluster.wait.aligned;"   ::: "memory");

    uint32_t ph0 = 0, ph1 = 0;
    const uint32_t my_off = (uint32_t)((ob * HH + c0 + oc) * 4);

    for (int t = 0; t < TT; ++t) {
        const int p = t & 1;
        float xbv = __ldcg(&g_xb[((size_t)t * BB + (b0 + ob)) * HH + c0 + oc]);

        if (t > 0) {
            if (p) { mbar_wait(mbar_u1, ph1); ph1 ^= 1; }
            else   { mbar_wait(mbar_u0, ph0); ph0 ^= 1; }
            if (tid == 0) {
                uint32_t mu = p ? mbar_u1 : mbar_u0;
                asm volatile("mbarrier.arrive.expect_tx.shared.b64 _, [%0], %1;"
                             :: "r"(mu), "r"((unsigned)STEP_TX) : "memory");
            }
        }

        const float* hb = p ? hb1 : hb0;

        float acc[4][4];
#pragma unroll
        for (int i = 0; i < 4; i++)
#pragma unroll
            for (int j = 0; j < 4; j++) acc[i][j] = 0.f;

        const int kb = ks * 32;
#pragma unroll
        for (int kc = 0; kc < 32; kc += 4) {
            const int k = kb + kc;
            float4 hv[4];
#pragma unroll
            for (int b = 0; b < 4; b++)
                hv[b] = *reinterpret_cast<const float4*>(&hb[b * HH + k]);
#pragma unroll
            for (int kk = 0; kk < 4; kk++) {
                float4 w4 = *reinterpret_cast<const float4*>(&Wt[(k + kk) * CPG + cq * 4]);
                float wj[4] = {w4.x, w4.y, w4.z, w4.w};
                float hk[4] = {hv[0].x, hv[1].x, hv[2].x, hv[3].x};
                if (kk == 1) { hk[0]=hv[0].y; hk[1]=hv[1].y; hk[2]=hv[2].y; hk[3]=hv[3].y; }
                if (kk == 2) { hk[0]=hv[0].z; hk[1]=hv[1].z; hk[2]=hv[2].z; hk[3]=hv[3].z; }
                if (kk == 3) { hk[0]=hv[0].w; hk[1]=hv[1].w; hk[2]=hv[2].w; hk[3]=hv[3].w; }
#pragma unroll
                for (int b = 0; b < 4; b++)
#pragma unroll
                    for (int j = 0; j < 4; j++)
                        acc[b][j] += hk[b] * wj[j];
            }
        }

#pragma unroll
        for (int b = 0; b < 4; ++b)
            *reinterpret_cast<float4*>(&red[ks * 256 + b * 64 + cq * 4]) =
                make_float4(acc[b][0], acc[b][1], acc[b][2], acc[b][3]);
        __syncthreads();   // S1

        float s = 0.f;
#pragma unroll
        for (int k2 = 0; k2 < 16; ++k2) s += red[k2 * 256 + tid];
        float v = tanhf(s + xbv);

        const size_t oidx = ((size_t)(b0 + ob) * TT + t) * HH + c0 + oc;
        if (use_g0out) {
            __nv_bfloat16 hb16 = __float2bfloat16_rn(v);
            g_ahi[oidx] = hb16;
            g_alo[oidx] = __float2bfloat16_rn(v - __bfloat162float(hb16));
        } else {
            out_param[oidx] = v;
        }
        if (t == TT - 1) hn[(size_t)(b0 + ob) * HH + c0 + oc] = v;

        if (t < TT - 1) {
            const uint32_t dst_l  = (p ? hb_u0 : hb_u1) + my_off;
            const uint32_t mbar_l = p ? mbar_u0 : mbar_u1;
            const uint32_t vb = __float_as_uint(v);
#pragma unroll
            for (int r = 0; r < GC; r++) {
                uint32_t da, ma;
                asm("mapa.shared::cluster.u32 %0, %1, %2;" : "=r"(da) : "r"(dst_l),  "r"(r));
                asm("mapa.shared::cluster.u32 %0, %1, %2;" : "=r"(ma) : "r"(mbar_l), "r"(r));
                asm volatile(
                    "st.async.shared::cluster.mbarrier::complete_tx::bytes.b32 [%0], %1, [%2];"
                    :: "r"(da), "r"(vb), "r"(ma) : "memory");
            }
        }
    }

    asm volatile("barrier.cluster.arrive.aligned;" ::: "memory");
    asm volatile("barrier.cluster.wait.aligned;"   ::: "memory");
}

// ------------------------------ launch --------------------------------------
extern "C" void kernel_launch(void* const* d_in, const int* in_sizes, int n_in,
                              void* d_out, int out_size)
{
    const float* x    = (const float*)d_in[0];
    const float* h0   = (const float*)d_in[1];
    const float* Wih0 = (const float*)d_in[2];
    const float* Whh0 = (const float*)d_in[3];
    const float* bih0 = (const float*)d_in[4];
    const float* bhh0 = (const float*)d_in[5];
    const float* Wih1 = (const float*)d_in[6];
    const float* Whh1 = (const float*)d_in[7];
    const float* bih1 = (const float*)d_in[8];
    const float* bhh1 = (const float*)d_in[9];

    float* out  = (float*)d_out;
    float* out1 = out;                       // [B,T,H]
    float* hn0  = out + (size_t)BTH;
    float* hn1  = hn0 + (size_t)BB * HH;

    static int smem_set = 0;
    if (!smem_set) {
        cudaFuncSetAttribute(rnn_rec, cudaFuncAttributeMaxDynamicSharedMemorySize,
                             REC_SMEM_BYTES);
        smem_set = 1;
    }

    __nv_bfloat16 *ahi, *alo, *whi0, *wlo0, *whi1, *wlo1;
    cudaGetSymbolAddress((void**)&ahi,  g_ahi);
    cudaGetSymbolAddress((void**)&alo,  g_alo);
    cudaGetSymbolAddress((void**)&whi0, g_whi0);
    cudaGetSymbolAddress((void**)&wlo0, g_wlo0);
    cudaGetSymbolAddress((void**)&whi1, g_whi1);
    cudaGetSymbolAddress((void**)&wlo1, g_wlo1);

    dim3 ggrid(HH / 64, (BB * TT) / MT);     // (8, 256)

    // Single merged weight-split launch.
    const int nb0 = (HH * IDIM + 255) / 256;
    const int nb1 = (HH * HH + 255) / 256;
    conv_split2<<<nb0 + nb1, 256>>>(Wih0, HH * IDIM, nb0, Wih1, HH * HH);

    // ---- layer 0 ----
    gemm_wmma<<<ggrid, 256>>>(x, nullptr, nullptr, whi0, wlo0, bih0, bhh0, IDIM, 0);
    rnn_rec<<<NCTA, THR, REC_SMEM_BYTES>>>(Whh0, h0, out1, hn0, 1);

    // ---- layer 1 ----
    gemm_wmma<<<ggrid, 256>>>(nullptr, ahi, alo, whi1, wlo1, bih1, bhh1, HH, 1);
    rnn_rec<<<NCTA, THR, REC_SMEM_BYTES>>>(Whh1, h0 + (size_t)BB * HH, out1, hn1, 0);
}

// round 16
// speedup vs baseline: 1.5931x; 1.5931x over previous
#include <cuda_runtime.h>
#include <cuda_bf16.h>
#include <mma.h>
#include <cstdint>

using namespace nvcuda;

// Problem dims (fixed)
#define BB   64
#define TT   512
#define IDIM 256
#define HH   512
#define BTH  (BB*TT*HH)

// Recurrence decomposition: 16 clusters (batch groups) x 8 CTAs (column groups)
#define GB   16
#define GC   8
#define BPG  4
#define CPG  64
#define NCTA (GB*GC)
#define THR  256

// ------------------------------ scratch ------------------------------------
__device__ float g_xb[TT*BB*HH];              // input projection [t][b][h]
__device__ __nv_bfloat16 g_ahi[BTH];          // layer-0 output, split hi
__device__ __nv_bfloat16 g_alo[BTH];          // layer-0 output, split lo
__device__ __nv_bfloat16 g_whi[HH*HH];        // W_ih split hi
__device__ __nv_bfloat16 g_wlo[HH*HH];        // W_ih split lo

// ------------------------------ split conversion (weights only) --------------
__global__ void conv_split(const float* __restrict__ s,
                           __nv_bfloat16* __restrict__ hi,
                           __nv_bfloat16* __restrict__ lo, int n)
{
    int i = blockIdx.x * blockDim.x + threadIdx.x;
    if (i < n) {
        float x = s[i];
        __nv_bfloat16 h = __float2bfloat16_rn(x);
        hi[i] = h;
        lo[i] = __float2bfloat16_rn(x - __bfloat162float(h));
    }
}

// ------------------------------ wmma GEMM (bf16 x3 split, fused A split) -----
// Y[t][b][n] = sum_k A[m][k]*W[n][k] + b1[n] + b2[n],  m = b*TT + t
// mode 0: A read as fp32 (Afp), hi/lo split done during smem staging.
// mode 1: A read from pre-split bf16 arrays (Ah/Al).
#define KC   64
#define LDS2 72

__global__ void __launch_bounds__(256) gemm_wmma(
    const float* __restrict__ Afp,
    const __nv_bfloat16* __restrict__ Ah, const __nv_bfloat16* __restrict__ Al,
    const __nv_bfloat16* __restrict__ Bh, const __nv_bfloat16* __restrict__ Bl,
    const float* __restrict__ b1, const float* __restrict__ b2,
    int K, int mode)
{
    __shared__ char raw[4 * 64 * LDS2 * 2];   // 36864 B
    __nv_bfloat16* sAh = reinterpret_cast<__nv_bfloat16*>(raw);
    __nv_bfloat16* sAl = sAh + 64 * LDS2;
    __nv_bfloat16* sBh = sAl + 64 * LDS2;
    __nv_bfloat16* sBl = sBh + 64 * LDS2;

    const int tid = threadIdx.x;
    const int nb  = blockIdx.x;
    const int mb  = blockIdx.y;
    const int wid = tid >> 5;
    const int wr  = wid & 3;
    const int wc  = wid >> 2;

    wmma::fragment<wmma::accumulator, 16, 16, 16, float> acc[2];
    wmma::fill_fragment(acc[0], 0.0f);
    wmma::fill_fragment(acc[1], 0.0f);

    const int row = tid >> 2;            // 0..63
    const int seg = (tid & 3) * 16;      // 16 elems per thread

    for (int k0 = 0; k0 < K; k0 += KC) {
        __syncthreads();
        // ---- stage A ----
        if (mode == 0) {
            const float4* src = reinterpret_cast<const float4*>(
                Afp + (size_t)(mb*64 + row)*K + k0 + seg);
            float v[16];
#pragma unroll
            for (int j = 0; j < 4; ++j) {
                float4 f = src[j];
                v[j*4+0] = f.x; v[j*4+1] = f.y; v[j*4+2] = f.z; v[j*4+3] = f.w;
            }
            uint32_t ph[8], pl[8];
#pragma unroll
            for (int i = 0; i < 8; ++i) {
                __nv_bfloat16 h0b = __float2bfloat16_rn(v[2*i]);
                __nv_bfloat16 h1b = __float2bfloat16_rn(v[2*i+1]);
                __nv_bfloat16 l0b = __float2bfloat16_rn(v[2*i]   - __bfloat162float(h0b));
                __nv_bfloat16 l1b = __float2bfloat16_rn(v[2*i+1] - __bfloat162float(h1b));
                ph[i] = (uint32_t)__bfloat16_as_ushort(h0b) |
                        ((uint32_t)__bfloat16_as_ushort(h1b) << 16);
                pl[i] = (uint32_t)__bfloat16_as_ushort(l0b) |
                        ((uint32_t)__bfloat16_as_ushort(l1b) << 16);
            }
            uint4* dH = reinterpret_cast<uint4*>(sAh + row*LDS2 + seg);
            uint4* dL = reinterpret_cast<uint4*>(sAl + row*LDS2 + seg);
            dH[0] = make_uint4(ph[0],ph[1],ph[2],ph[3]);
            dH[1] = make_uint4(ph[4],ph[5],ph[6],ph[7]);
            dL[0] = make_uint4(pl[0],pl[1],pl[2],pl[3]);
            dL[1] = make_uint4(pl[4],pl[5],pl[6],pl[7]);
        } else {
            const uint4* a_h = reinterpret_cast<const uint4*>(Ah + (size_t)(mb*64 + row)*K + k0 + seg);
            const uint4* a_l = reinterpret_cast<const uint4*>(Al + (size_t)(mb*64 + row)*K + k0 + seg);
            uint4* dH = reinterpret_cast<uint4*>(sAh + row*LDS2 + seg);
            uint4* dL = reinterpret_cast<uint4*>(sAl + row*LDS2 + seg);
            dH[0] = a_h[0]; dH[1] = a_h[1];
            dL[0] = a_l[0]; dL[1] = a_l[1];
        }
        // ---- stage B (always pre-split) ----
        {
            const uint4* b_h = reinterpret_cast<const uint4*>(Bh + (size_t)(nb*64 + row)*K + k0 + seg);
            const uint4* b_l = reinterpret_cast<const uint4*>(Bl + (size_t)(nb*64 + row)*K + k0 + seg);
            uint4* dH = reinterpret_cast<uint4*>(sBh + row*LDS2 + seg);
            uint4* dL = reinterpret_cast<uint4*>(sBl + row*LDS2 + seg);
            dH[0] = b_h[0]; dH[1] = b_h[1];
            dL[0] = b_l[0]; dL[1] = b_l[1];
        }
        __syncthreads();

#pragma unroll
        for (int kk = 0; kk < KC / 16; ++kk) {
            wmma::fragment<wmma::matrix_a, 16, 16, 16, __nv_bfloat16, wmma::row_major> fa_h, fa_l;
            wmma::load_matrix_sync(fa_h, sAh + (wr*16)*LDS2 + kk*16, LDS2);
            wmma::load_matrix_sync(fa_l, sAl + (wr*16)*LDS2 + kk*16, LDS2);
#pragma unroll
            for (int ns = 0; ns < 2; ++ns) {
                wmma::fragment<wmma::matrix_b, 16, 16, 16, __nv_bfloat16, wmma::col_major> fb_h, fb_l;
                wmma::load_matrix_sync(fb_h, sBh + (wc*32 + ns*16)*LDS2 + kk*16, LDS2);
                wmma::load_matrix_sync(fb_l, sBl + (wc*32 + ns*16)*LDS2 + kk*16, LDS2);
                wmma::mma_sync(acc[ns], fa_h, fb_h, acc[ns]);
                wmma::mma_sync(acc[ns], fa_h, fb_l, acc[ns]);
                wmma::mma_sync(acc[ns], fa_l, fb_h, acc[ns]);
            }
        }
    }

    __syncthreads();
    float* Cs = reinterpret_cast<float*>(raw);
    wmma::store_matrix_sync(Cs + (wr*16)*LDS2 + wc*32 + 0,  acc[0], LDS2, wmma::mem_row_major);
    wmma::store_matrix_sync(Cs + (wr*16)*LDS2 + wc*32 + 16, acc[1], LDS2, wmma::mem_row_major);
    __syncthreads();

    const int col4 = (tid & 15) * 4;
    const int n0   = nb * 64 + col4;
    float4 bias;
    bias.x = b1[n0 + 0] + b2[n0 + 0];
    bias.y = b1[n0 + 1] + b2[n0 + 1];
    bias.z = b1[n0 + 2] + b2[n0 + 2];
    bias.w = b1[n0 + 3] + b2[n0 + 3];

#pragma unroll
    for (int rr = 0; rr < 4; ++rr) {
        int r  = rr * 16 + (tid >> 4);
        int m  = mb * 64 + r;
        int b_ = m >> 9;
        int t_ = m & (TT - 1);
        float4 o;
        o.x = Cs[r * LDS2 + col4 + 0] + bias.x;
        o.y = Cs[r * LDS2 + col4 + 1] + bias.y;
        o.z = Cs[r * LDS2 + col4 + 2] + bias.z;
        o.w = Cs[r * LDS2 + col4 + 3] + bias.w;
        *reinterpret_cast<float4*>(&g_xb[((size_t)t_ * BB + b_) * HH + n0]) = o;
    }
}

// ------------------------------ helpers -------------------------------------
__device__ __forceinline__ uint32_t smem_u32(const void* p) {
    uint32_t a;
    asm("{ .reg .u64 t; cvta.to.shared.u64 t, %1; cvt.u32.u64 %0, t; }"
        : "=r"(a) : "l"(p));
    return a;
}

__device__ __forceinline__ void mbar_wait(uint32_t mbar, uint32_t parity) {
    asm volatile(
        "{\n\t"
        ".reg .pred P;\n\t"
        "WL%=:\n\t"
        "mbarrier.try_wait.parity.acquire.cluster.shared::cta.b64 P, [%0], %1;\n\t"
        "@!P bra WL%=;\n\t"
        "}"
        :: "r"(mbar), "r"(parity) : "memory");
}

// ------------------------------ recurrence (R9 core; layer-0 writes bf16 split)
#define SM_W    (HH*CPG)
#define SM_HB   (SM_W)
#define SM_RED  (SM_W + 2*BPG*HH)
#define SM_MBAR (SM_RED + 16*256)
#define REC_SMEM_BYTES ((SM_MBAR + 8) * 4)

#define STEP_TX (GC * 256 * 4)

__global__ void __launch_bounds__(THR, 1) __cluster_dims__(GC, 1, 1)
rnn_rec(const float* __restrict__ Whh,
        const float* __restrict__ h0,
        float* __restrict__ out_param,
        float* __restrict__ hn,
        int use_g0out)
{
    extern __shared__ float sm[];
    float* Wt  = sm;
    float* hb0 = sm + SM_HB;
    float* hb1 = hb0 + BPG * HH;
    float* red = sm + SM_RED;
    uint64_t* mbar = reinterpret_cast<uint64_t*>(sm + SM_MBAR);

    const int tid = threadIdx.x;
    uint32_t cg;
    asm("mov.u32 %0, %%cluster_ctarank;" : "=r"(cg));
    const int bg  = blockIdx.x >> 3;
    const int c0  = (int)cg * CPG;
    const int b0  = bg * BPG;
    const int ks  = tid >> 4;
    const int cq  = tid & 15;
    const int ob  = tid >> 6;
    const int oc  = tid & 63;

    const uint32_t mbar_u0 = smem_u32(&mbar[0]);
    const uint32_t mbar_u1 = smem_u32(&mbar[1]);
    const uint32_t hb_u0   = smem_u32(hb0);
    const uint32_t hb_u1   = smem_u32(hb1);

    for (int idx = tid; idx < CPG * (HH / 4); idx += 256) {
        int c  = idx & (CPG - 1);
        int k4 = idx >> 6;
        float4 w = *reinterpret_cast<const float4*>(Whh + (size_t)(c0 + c) * HH + k4 * 4);
        Wt[(k4 * 4 + 0) * CPG + c] = w.x;
        Wt[(k4 * 4 + 1) * CPG + c] = w.y;
        Wt[(k4 * 4 + 2) * CPG + c] = w.z;
        Wt[(k4 * 4 + 3) * CPG + c] = w.w;
    }
    {
        float4* d = reinterpret_cast<float4*>(hb0);
        const float4* s = reinterpret_cast<const float4*>(h0 + (size_t)b0 * HH);
        d[tid]       = s[tid];
        d[tid + 256] = s[tid + 256];
    }
    if (tid == 0) {
        asm volatile("mbarrier.init.shared.b64 [%0], %1;" :: "r"(mbar_u0), "r"(1u) : "memory");
        asm volatile("mbarrier.init.shared.b64 [%0], %1;" :: "r"(mbar_u1), "r"(1u) : "memory");
        asm volatile("mbarrier.arrive.expect_tx.shared.b64 _, [%0], %1;"
                     :: "r"(mbar_u0), "r"((unsigned)STEP_TX) : "memory");
        asm volatile("mbarrier.arrive.expect_tx.shared.b64 _, [%0], %1;"
                     :: "r"(mbar_u1), "r"((unsigned)STEP_TX) : "memory");
    }
    __syncthreads();
    asm volatile("barrier.cluster.arrive.aligned;" ::: "memory");
    asm volatile("barrier.cluster.wait.aligned;"   ::: "memory");

    uint32_t ph0 = 0, ph1 = 0;
    const uint32_t my_off = (uint32_t)((ob * HH + c0 + oc) * 4);

    for (int t = 0; t < TT; ++t) {
        const int p = t & 1;
        float xbv = __ldcg(&g_xb[((size_t)t * BB + (b0 + ob)) * HH + c0 + oc]);

        if (t > 0) {
            if (p) { mbar_wait(mbar_u1, ph1); ph1 ^= 1; }
            else   { mbar_wait(mbar_u0, ph0); ph0 ^= 1; }
            if (tid == 0) {
                uint32_t mu = p ? mbar_u1 : mbar_u0;
                asm volatile("mbarrier.arrive.expect_tx.shared.b64 _, [%0], %1;"
                             :: "r"(mu), "r"((unsigned)STEP_TX) : "memory");
            }
        }

        const float* hb = p ? hb1 : hb0;

        float acc[4][4];
#pragma unroll
        for (int i = 0; i < 4; i++)
#pragma unroll
            for (int j = 0; j < 4; j++) acc[i][j] = 0.f;

        const int kb = ks * 32;
#pragma unroll
        for (int kc = 0; kc < 32; kc += 4) {
            const int k = kb + kc;
            float4 hv[4];
#pragma unroll
            for (int b = 0; b < 4; b++)
                hv[b] = *reinterpret_cast<const float4*>(&hb[b * HH + k]);
#pragma unroll
            for (int kk = 0; kk < 4; kk++) {
                float4 w4 = *reinterpret_cast<const float4*>(&Wt[(k + kk) * CPG + cq * 4]);
                float wj[4] = {w4.x, w4.y, w4.z, w4.w};
                float hk[4] = {hv[0].x, hv[1].x, hv[2].x, hv[3].x};
                if (kk == 1) { hk[0]=hv[0].y; hk[1]=hv[1].y; hk[2]=hv[2].y; hk[3]=hv[3].y; }
                if (kk == 2) { hk[0]=hv[0].z; hk[1]=hv[1].z; hk[2]=hv[2].z; hk[3]=hv[3].z; }
                if (kk == 3) { hk[0]=hv[0].w; hk[1]=hv[1].w; hk[2]=hv[2].w; hk[3]=hv[3].w; }
#pragma unroll
                for (int b = 0; b < 4; b++)
#pragma unroll
                    for (int j = 0; j < 4; j++)
                        acc[b][j] += hk[b] * wj[j];
            }
        }

#pragma unroll
        for (int b = 0; b < 4; ++b)
            *reinterpret_cast<float4*>(&red[ks * 256 + b * 64 + cq * 4]) =
                make_float4(acc[b][0], acc[b][1], acc[b][2], acc[b][3]);
        __syncthreads();   // S1

        float s = 0.f;
#pragma unroll
        for (int k2 = 0; k2 < 16; ++k2) s += red[k2 * 256 + tid];
        float v = tanhf(s + xbv);

        const size_t oidx = ((size_t)(b0 + ob) * TT + t) * HH + c0 + oc;
        if (use_g0out) {
            // layer 0: write output directly as bf16 hi/lo split (gemm1 input)
            __nv_bfloat16 hb16 = __float2bfloat16_rn(v);
            g_ahi[oidx] = hb16;
            g_alo[oidx] = __float2bfloat16_rn(v - __bfloat162float(hb16));
        } else {
            out_param[oidx] = v;
        }
        if (t == TT - 1) hn[(size_t)(b0 + ob) * HH + c0 + oc] = v;

        if (t < TT - 1) {
            const uint32_t dst_l  = (p ? hb_u0 : hb_u1) + my_off;
            const uint32_t mbar_l = p ? mbar_u0 : mbar_u1;
            const uint32_t vb = __float_as_uint(v);
#pragma unroll
            for (int r = 0; r < GC; r++) {
                uint32_t da, ma;
                asm("mapa.shared::cluster.u32 %0, %1, %2;" : "=r"(da) : "r"(dst_l),  "r"(r));
                asm("mapa.shared::cluster.u32 %0, %1, %2;" : "=r"(ma) : "r"(mbar_l), "r"(r));
                asm volatile(
                    "st.async.shared::cluster.mbarrier::complete_tx::bytes.b32 [%0], %1, [%2];"
                    :: "r"(da), "r"(vb), "r"(ma) : "memory");
            }
        }
    }

    asm volatile("barrier.cluster.arrive.aligned;" ::: "memory");
    asm volatile("barrier.cluster.wait.aligned;"   ::: "memory");
}

// ------------------------------ launch --------------------------------------
extern "C" void kernel_launch(void* const* d_in, const int* in_sizes, int n_in,
                              void* d_out, int out_size)
{
    const float* x    = (const float*)d_in[0];
    const float* h0   = (const float*)d_in[1];
    const float* Wih0 = (const float*)d_in[2];
    const float* Whh0 = (const float*)d_in[3];
    const float* bih0 = (const float*)d_in[4];
    const float* bhh0 = (const float*)d_in[5];
    const float* Wih1 = (const float*)d_in[6];
    const float* Whh1 = (const float*)d_in[7];
    const float* bih1 = (const float*)d_in[8];
    const float* bhh1 = (const float*)d_in[9];

    float* out  = (float*)d_out;
    float* out1 = out;                       // [B,T,H]
    float* hn0  = out + (size_t)BTH;
    float* hn1  = hn0 + (size_t)BB * HH;

    static int smem_set = 0;
    if (!smem_set) {
        cudaFuncSetAttribute(rnn_rec, cudaFuncAttributeMaxDynamicSharedMemorySize,
                             REC_SMEM_BYTES);
        smem_set = 1;
    }

    __nv_bfloat16 *ahi, *alo, *whi, *wlo;
    cudaGetSymbolAddress((void**)&ahi, g_ahi);
    cudaGetSymbolAddress((void**)&alo, g_alo);
    cudaGetSymbolAddress((void**)&whi, g_whi);
    cudaGetSymbolAddress((void**)&wlo, g_wlo);

    dim3 ggrid(HH / 64, (BB * TT) / 64);     // (8, 512)

    // ---- layer 0 ----
    conv_split<<<(HH*IDIM + 255)/256, 256>>>(Wih0, whi, wlo, HH*IDIM);
    gemm_wmma<<<ggrid, 256>>>(x, nullptr, nullptr, whi, wlo, bih0, bhh0, IDIM, 0);
    rnn_rec<<<NCTA, THR, REC_SMEM_BYTES>>>(Whh0, h0, out1, hn0, 1);

    // ---- layer 1 ----
    conv_split<<<(HH*HH + 255)/256, 256>>>(Wih1, whi, wlo, HH*HH);
    gemm_wmma<<<ggrid, 256>>>(nullptr, ahi, alo, whi, wlo, bih1, bhh1, HH, 1);
    rnn_rec<<<NCTA, THR, REC_SMEM_BYTES>>>(Whh1, h0 + (size_t)BB * HH, out1, hn1, 0);
}

// round 17
// speedup vs baseline: 1.6044x; 1.0071x over previous
#include <cuda_runtime.h>
#include <cuda_bf16.h>
#include <mma.h>
#include <cstdint>

using namespace nvcuda;

// Problem dims (fixed)
#define BB   64
#define TT   512
#define IDIM 256
#define HH   512
#define BTH  (BB*TT*HH)

// Recurrence decomposition: 16 clusters (batch groups) x 8 CTAs (column groups)
#define GB   16
#define GC   8
#define BPG  4
#define CPG  64
#define NCTA (GB*GC)
#define THR  256

// ------------------------------ scratch ------------------------------------
__device__ float g_xb[TT*BB*HH];              // input projection [t][b][h]
__device__ __nv_bfloat16 g_ahi[BTH];          // layer-0 output, split hi
__device__ __nv_bfloat16 g_alo[BTH];          // layer-0 output, split lo
__device__ __nv_bfloat16 g_whi[HH*HH];        // W_ih split hi
__device__ __nv_bfloat16 g_wlo[HH*HH];        // W_ih split lo

// ------------------------------ split conversion (weights only) --------------
__global__ void conv_split(const float* __restrict__ s,
                           __nv_bfloat16* __restrict__ hi,
                           __nv_bfloat16* __restrict__ lo, int n)
{
    int i = blockIdx.x * blockDim.x + threadIdx.x;
    if (i < n) {
        float x = s[i];
        __nv_bfloat16 h = __float2bfloat16_rn(x);
        hi[i] = h;
        lo[i] = __float2bfloat16_rn(x - __bfloat162float(h));
    }
}

// ------------------------------ fast tanh -----------------------------------
// tanh(x) = (e^{2x}-1)/(e^{2x}+1); clamp keeps e^{2x} finite (tanh(15)=1 in fp32).
// MUFU.EX2 + MUFU.RCP chain (~44 cyc) vs tanhf's ~80; rel err ~1e-6.
__device__ __forceinline__ float fast_tanh(float x) {
    float cx = fminf(fmaxf(x, -15.f), 15.f);
    float e  = __expf(2.f * cx);
    return __fdividef(e - 1.f, e + 1.f);
}

// ------------------------------ wmma GEMM (bf16 x3 split, fused A split) -----
// Y[t][b][n] = sum_k A[m][k]*W[n][k] + b1[n] + b2[n],  m = b*TT + t
// mode 0: A read as fp32 (Afp), hi/lo split done during smem staging.
// mode 1: A read from pre-split bf16 arrays (Ah/Al).
#define KC   64
#define LDS2 72

__global__ void __launch_bounds__(256) gemm_wmma(
    const float* __restrict__ Afp,
    const __nv_bfloat16* __restrict__ Ah, const __nv_bfloat16* __restrict__ Al,
    const __nv_bfloat16* __restrict__ Bh, const __nv_bfloat16* __restrict__ Bl,
    const float* __restrict__ b1, const float* __restrict__ b2,
    int K, int mode)
{
    __shared__ char raw[4 * 64 * LDS2 * 2];   // 36864 B
    __nv_bfloat16* sAh = reinterpret_cast<__nv_bfloat16*>(raw);
    __nv_bfloat16* sAl = sAh + 64 * LDS2;
    __nv_bfloat16* sBh = sAl + 64 * LDS2;
    __nv_bfloat16* sBl = sBh + 64 * LDS2;

    const int tid = threadIdx.x;
    const int nb  = blockIdx.x;
    const int mb  = blockIdx.y;
    const int wid = tid >> 5;
    const int wr  = wid & 3;
    const int wc  = wid >> 2;

    wmma::fragment<wmma::accumulator, 16, 16, 16, float> acc[2];
    wmma::fill_fragment(acc[0], 0.0f);
    wmma::fill_fragment(acc[1], 0.0f);

    const int row = tid >> 2;            // 0..63
    const int seg = (tid & 3) * 16;      // 16 elems per thread

    for (int k0 = 0; k0 < K; k0 += KC) {
        __syncthreads();
        // ---- stage A ----
        if (mode == 0) {
            const float4* src = reinterpret_cast<const float4*>(
                Afp + (size_t)(mb*64 + row)*K + k0 + seg);
            float v[16];
#pragma unroll
            for (int j = 0; j < 4; ++j) {
                float4 f = src[j];
                v[j*4+0] = f.x; v[j*4+1] = f.y; v[j*4+2] = f.z; v[j*4+3] = f.w;
            }
            uint32_t ph[8], pl[8];
#pragma unroll
            for (int i = 0; i < 8; ++i) {
                __nv_bfloat16 h0b = __float2bfloat16_rn(v[2*i]);
                __nv_bfloat16 h1b = __float2bfloat16_rn(v[2*i+1]);
                __nv_bfloat16 l0b = __float2bfloat16_rn(v[2*i]   - __bfloat162float(h0b));
                __nv_bfloat16 l1b = __float2bfloat16_rn(v[2*i+1] - __bfloat162float(h1b));
                ph[i] = (uint32_t)__bfloat16_as_ushort(h0b) |
                        ((uint32_t)__bfloat16_as_ushort(h1b) << 16);
                pl[i] = (uint32_t)__bfloat16_as_ushort(l0b) |
                        ((uint32_t)__bfloat16_as_ushort(l1b) << 16);
            }
            uint4* dH = reinterpret_cast<uint4*>(sAh + row*LDS2 + seg);
            uint4* dL = reinterpret_cast<uint4*>(sAl + row*LDS2 + seg);
            dH[0] = make_uint4(ph[0],ph[1],ph[2],ph[3]);
            dH[1] = make_uint4(ph[4],ph[5],ph[6],ph[7]);
            dL[0] = make_uint4(pl[0],pl[1],pl[2],pl[3]);
            dL[1] = make_uint4(pl[4],pl[5],pl[6],pl[7]);
        } else {
            const uint4* a_h = reinterpret_cast<const uint4*>(Ah + (size_t)(mb*64 + row)*K + k0 + seg);
            const uint4* a_l = reinterpret_cast<const uint4*>(Al + (size_t)(mb*64 + row)*K + k0 + seg);
            uint4* dH = reinterpret_cast<uint4*>(sAh + row*LDS2 + seg);
            uint4* dL = reinterpret_cast<uint4*>(sAl + row*LDS2 + seg);
            dH[0] = a_h[0]; dH[1] = a_h[1];
            dL[0] = a_l[0]; dL[1] = a_l[1];
        }
        // ---- stage B (always pre-split) ----
        {
            const uint4* b_h = reinterpret_cast<const uint4*>(Bh + (size_t)(nb*64 + row)*K + k0 + seg);
            const uint4* b_l = reinterpret_cast<const uint4*>(Bl + (size_t)(nb*64 + row)*K + k0 + seg);
            uint4* dH = reinterpret_cast<uint4*>(sBh + row*LDS2 + seg);
            uint4* dL = reinterpret_cast<uint4*>(sBl + row*LDS2 + seg);
            dH[0] = b_h[0]; dH[1] = b_h[1];
            dL[0] = b_l[0]; dL[1] = b_l[1];
        }
        __syncthreads();

#pragma unroll
        for (int kk = 0; kk < KC / 16; ++kk) {
            wmma::fragment<wmma::matrix_a, 16, 16, 16, __nv_bfloat16, wmma::row_major> fa_h, fa_l;
            wmma::load_matrix_sync(fa_h, sAh + (wr*16)*LDS2 + kk*16, LDS2);
            wmma::load_matrix_sync(fa_l, sAl + (wr*16)*LDS2 + kk*16, LDS2);
#pragma unroll
            for (int ns = 0; ns < 2; ++ns) {
                wmma::fragment<wmma::matrix_b, 16, 16, 16, __nv_bfloat16, wmma::col_major> fb_h, fb_l;
                wmma::load_matrix_sync(fb_h, sBh + (wc*32 + ns*16)*LDS2 + kk*16, LDS2);
                wmma::load_matrix_sync(fb_l, sBl + (wc*32 + ns*16)*LDS2 + kk*16, LDS2);
                wmma::mma_sync(acc[ns], fa_h, fb_h, acc[ns]);
                wmma::mma_sync(acc[ns], fa_h, fb_l, acc[ns]);
                wmma::mma_sync(acc[ns], fa_l, fb_h, acc[ns]);
            }
        }
    }

    __syncthreads();
    float* Cs = reinterpret_cast<float*>(raw);
    wmma::store_matrix_sync(Cs + (wr*16)*LDS2 + wc*32 + 0,  acc[0], LDS2, wmma::mem_row_major);
    wmma::store_matrix_sync(Cs + (wr*16)*LDS2 + wc*32 + 16, acc[1], LDS2, wmma::mem_row_major);
    __syncthreads();

    const int col4 = (tid & 15) * 4;
    const int n0   = nb * 64 + col4;
    float4 bias;
    bias.x = b1[n0 + 0] + b2[n0 + 0];
    bias.y = b1[n0 + 1] + b2[n0 + 1];
    bias.z = b1[n0 + 2] + b2[n0 + 2];
    bias.w = b1[n0 + 3] + b2[n0 + 3];

#pragma unroll
    for (int rr = 0; rr < 4; ++rr) {
        int r  = rr * 16 + (tid >> 4);
        int m  = mb * 64 + r;
        int b_ = m >> 9;
        int t_ = m & (TT - 1);
        float4 o;
        o.x = Cs[r * LDS2 + col4 + 0] + bias.x;
        o.y = Cs[r * LDS2 + col4 + 1] + bias.y;
        o.z = Cs[r * LDS2 + col4 + 2] + bias.z;
        o.w = Cs[r * LDS2 + col4 + 3] + bias.w;
        *reinterpret_cast<float4*>(&g_xb[((size_t)t_ * BB + b_) * HH + n0]) = o;
    }
}

// ------------------------------ helpers -------------------------------------
__device__ __forceinline__ uint32_t smem_u32(const void* p) {
    uint32_t a;
    asm("{ .reg .u64 t; cvta.to.shared.u64 t, %1; cvt.u32.u64 %0, t; }"
        : "=r"(a) : "l"(p));
    return a;
}

__device__ __forceinline__ void mbar_wait(uint32_t mbar, uint32_t parity) {
    asm volatile(
        "{\n\t"
        ".reg .pred P;\n\t"
        "WL%=:\n\t"
        "mbarrier.try_wait.parity.acquire.cluster.shared::cta.b64 P, [%0], %1;\n\t"
        "@!P bra WL%=;\n\t"
        "}"
        :: "r"(mbar), "r"(parity) : "memory");
}

// ------------------------------ recurrence (R10 core + fast tanh, send-first)
#define SM_W    (HH*CPG)
#define SM_HB   (SM_W)
#define SM_RED  (SM_W + 2*BPG*HH)
#define SM_MBAR (SM_RED + 16*256)
#define REC_SMEM_BYTES ((SM_MBAR + 8) * 4)

#define STEP_TX (GC * 256 * 4)

__global__ void __launch_bounds__(THR, 1) __cluster_dims__(GC, 1, 1)
rnn_rec(const float* __restrict__ Whh,
        const float* __restrict__ h0,
        float* __restrict__ out_param,
        float* __restrict__ hn,
        int use_g0out)
{
    extern __shared__ float sm[];
    float* Wt  = sm;
    float* hb0 = sm + SM_HB;
    float* hb1 = hb0 + BPG * HH;
    float* red = sm + SM_RED;
    uint64_t* mbar = reinterpret_cast<uint64_t*>(sm + SM_MBAR);

    const int tid = threadIdx.x;
    uint32_t cg;
    asm("mov.u32 %0, %%cluster_ctarank;" : "=r"(cg));
    const int bg  = blockIdx.x >> 3;
    const int c0  = (int)cg * CPG;
    const int b0  = bg * BPG;
    const int ks  = tid >> 4;
    const int cq  = tid & 15;
    const int ob  = tid >> 6;
    const int oc  = tid & 63;

    const uint32_t mbar_u0 = smem_u32(&mbar[0]);
    const uint32_t mbar_u1 = smem_u32(&mbar[1]);
    const uint32_t hb_u0   = smem_u32(hb0);
    const uint32_t hb_u1   = smem_u32(hb1);

    for (int idx = tid; idx < CPG * (HH / 4); idx += 256) {
        int c  = idx & (CPG - 1);
        int k4 = idx >> 6;
        float4 w = *reinterpret_cast<const float4*>(Whh + (size_t)(c0 + c) * HH + k4 * 4);
        Wt[(k4 * 4 + 0) * CPG + c] = w.x;
        Wt[(k4 * 4 + 1) * CPG + c] = w.y;
        Wt[(k4 * 4 + 2) * CPG + c] = w.z;
        Wt[(k4 * 4 + 3) * CPG + c] = w.w;
    }
    {
        float4* d = reinterpret_cast<float4*>(hb0);
        const float4* s = reinterpret_cast<const float4*>(h0 + (size_t)b0 * HH);
        d[tid]       = s[tid];
        d[tid + 256] = s[tid + 256];
    }
    if (tid == 0) {
        asm volatile("mbarrier.init.shared.b64 [%0], %1;" :: "r"(mbar_u0), "r"(1u) : "memory");
        asm volatile("mbarrier.init.shared.b64 [%0], %1;" :: "r"(mbar_u1), "r"(1u) : "memory");
        asm volatile("mbarrier.arrive.expect_tx.shared.b64 _, [%0], %1;"
                     :: "r"(mbar_u0), "r"((unsigned)STEP_TX) : "memory");
        asm volatile("mbarrier.arrive.expect_tx.shared.b64 _, [%0], %1;"
                     :: "r"(mbar_u1), "r"((unsigned)STEP_TX) : "memory");
    }
    __syncthreads();
    asm volatile("barrier.cluster.arrive.aligned;" ::: "memory");
    asm volatile("barrier.cluster.wait.aligned;"   ::: "memory");

    uint32_t ph0 = 0, ph1 = 0;
    const uint32_t my_off = (uint32_t)((ob * HH + c0 + oc) * 4);

    for (int t = 0; t < TT; ++t) {
        const int p = t & 1;
        float xbv = __ldcg(&g_xb[((size_t)t * BB + (b0 + ob)) * HH + c0 + oc]);

        if (t > 0) {
            if (p) { mbar_wait(mbar_u1, ph1); ph1 ^= 1; }
            else   { mbar_wait(mbar_u0, ph0); ph0 ^= 1; }
            if (tid == 0) {
                uint32_t mu = p ? mbar_u1 : mbar_u0;
                asm volatile("mbarrier.arrive.expect_tx.shared.b64 _, [%0], %1;"
                             :: "r"(mu), "r"((unsigned)STEP_TX) : "memory");
            }
        }

        const float* hb = p ? hb1 : hb0;

        float acc[4][4];
#pragma unroll
        for (int i = 0; i < 4; i++)
#pragma unroll
            for (int j = 0; j < 4; j++) acc[i][j] = 0.f;

        const int kb = ks * 32;
#pragma unroll
        for (int kc = 0; kc < 32; kc += 4) {
            const int k = kb + kc;
            float4 hv[4];
#pragma unroll
            for (int b = 0; b < 4; b++)
                hv[b] = *reinterpret_cast<const float4*>(&hb[b * HH + k]);
#pragma unroll
            for (int kk = 0; kk < 4; kk++) {
                float4 w4 = *reinterpret_cast<const float4*>(&Wt[(k + kk) * CPG + cq * 4]);
                float wj[4] = {w4.x, w4.y, w4.z, w4.w};
                float hk[4] = {hv[0].x, hv[1].x, hv[2].x, hv[3].x};
                if (kk == 1) { hk[0]=hv[0].y; hk[1]=hv[1].y; hk[2]=hv[2].y; hk[3]=hv[3].y; }
                if (kk == 2) { hk[0]=hv[0].z; hk[1]=hv[1].z; hk[2]=hv[2].z; hk[3]=hv[3].z; }
                if (kk == 3) { hk[0]=hv[0].w; hk[1]=hv[1].w; hk[2]=hv[2].w; hk[3]=hv[3].w; }
#pragma unroll
                for (int b = 0; b < 4; b++)
#pragma unroll
                    for (int j = 0; j < 4; j++)
                        acc[b][j] += hk[b] * wj[j];
            }
        }

#pragma unroll
        for (int b = 0; b < 4; ++b)
            *reinterpret_cast<float4*>(&red[ks * 256 + b * 64 + cq * 4]) =
                make_float4(acc[b][0], acc[b][1], acc[b][2], acc[b][3]);
        __syncthreads();   // S1

        float s = 0.f;
#pragma unroll
        for (int k2 = 0; k2 < 16; ++k2) s += red[k2 * 256 + tid];
        float v = fast_tanh(s + xbv);

        // Sends FIRST (they gate the peers' next step; outputs gate nothing).
        if (t < TT - 1) {
            const uint32_t dst_l  = (p ? hb_u0 : hb_u1) + my_off;
            const uint32_t mbar_l = p ? mbar_u0 : mbar_u1;
            const uint32_t vb = __float_as_uint(v);
#pragma unroll
            for (int r = 0; r < GC; r++) {
                uint32_t da, ma;
                asm("mapa.shared::cluster.u32 %0, %1, %2;" : "=r"(da) : "r"(dst_l),  "r"(r));
                asm("mapa.shared::cluster.u32 %0, %1, %2;" : "=r"(ma) : "r"(mbar_l), "r"(r));
                asm volatile(
                    "st.async.shared::cluster.mbarrier::complete_tx::bytes.b32 [%0], %1, [%2];"
                    :: "r"(da), "r"(vb), "r"(ma) : "memory");
            }
        }

        const size_t oidx = ((size_t)(b0 + ob) * TT + t) * HH + c0 + oc;
        if (use_g0out) {
            // layer 0: write output directly as bf16 hi/lo split (gemm1 input)
            __nv_bfloat16 hb16 = __float2bfloat16_rn(v);
            g_ahi[oidx] = hb16;
            g_alo[oidx] = __float2bfloat16_rn(v - __bfloat162float(hb16));
        } else {
            out_param[oidx] = v;
        }
        if (t == TT - 1) hn[(size_t)(b0 + ob) * HH + c0 + oc] = v;
    }

    asm volatile("barrier.cluster.arrive.aligned;" ::: "memory");
    asm volatile("barrier.cluster.wait.aligned;"   ::: "memory");
}

// ------------------------------ launch --------------------------------------
extern "C" void kernel_launch(void* const* d_in, const int* in_sizes, int n_in,
                              void* d_out, int out_size)
{
    const float* x    = (const float*)d_in[0];
    const float* h0   = (const float*)d_in[1];
    const float* Wih0 = (const float*)d_in[2];
    const float* Whh0 = (const float*)d_in[3];
    const float* bih0 = (const float*)d_in[4];
    const float* bhh0 = (const float*)d_in[5];
    const float* Wih1 = (const float*)d_in[6];
    const float* Whh1 = (const float*)d_in[7];
    const float* bih1 = (const float*)d_in[8];
    const float* bhh1 = (const float*)d_in[9];

    float* out  = (float*)d_out;
    float* out1 = out;                       // [B,T,H]
    float* hn0  = out + (size_t)BTH;
    float* hn1  = hn0 + (size_t)BB * HH;

    static int smem_set = 0;
    if (!smem_set) {
        cudaFuncSetAttribute(rnn_rec, cudaFuncAttributeMaxDynamicSharedMemorySize,
                             REC_SMEM_BYTES);
        smem_set = 1;
    }

    __nv_bfloat16 *ahi, *alo, *whi, *wlo;
    cudaGetSymbolAddress((void**)&ahi, g_ahi);
    cudaGetSymbolAddress((void**)&alo, g_alo);
    cudaGetSymbolAddress((void**)&whi, g_whi);
    cudaGetSymbolAddress((void**)&wlo, g_wlo);

    dim3 ggrid(HH / 64, (BB * TT) / 64);     // (8, 512)

    // ---- layer 0 ----
    conv_split<<<(HH*IDIM + 255)/256, 256>>>(Wih0, whi, wlo, HH*IDIM);
    gemm_wmma<<<ggrid, 256>>>(x, nullptr, nullptr, whi, wlo, bih0, bhh0, IDIM, 0);
    rnn_rec<<<NCTA, THR, REC_SMEM_BYTES>>>(Whh0, h0, out1, hn0, 1);

    // ---- layer 1 ----
    conv_split<<<(HH*HH + 255)/256, 256>>>(Wih1, whi, wlo, HH*HH);
    gemm_wmma<<<ggrid, 256>>>(nullptr, ahi, alo, whi, wlo, bih1, bhh1, HH, 1);
    rnn_rec<<<NCTA, THR, REC_SMEM_BYTES>>>(Whh1, h0 + (size_t)BB * HH, out1, hn1, 0);
}